// round 2
// baseline (speedup 1.0000x reference)
#include <cuda_runtime.h>
#include <math.h>

#define Lc 4
#define Nn 8192
#define SPLITS 8
#define CHUNK (Nn/SPLITS)   // 1024

// ---- device scratch (no allocations allowed) ----
__device__ float4   g_E[2*Nn];              // XeT / SeT, one float4 per column
__device__ unsigned g_RsqBits[2];           // max ||xe||^2 as float bits
__device__ float4   g_pnum[2*SPLITS*Nn];    // partial numerators
__device__ float    g_pden[2*SPLITS*Nn];    // partial denominators
__device__ float    g_Z8[Nn*8];             // combined RHS for W2 GEMM (8192 x 8)
__device__ float    g_M[2*Lc*Nn];           // Mx flat | Ms flat

// ---------------------------------------------------------------- init
__global__ void k_init() {
    if (threadIdx.x < 2) g_RsqBits[threadIdx.x] = 0u;
}

// ---------------------------------------------------------------- prep: Xe, Se, R
__global__ void __launch_bounds__(256) k_prep(const float* __restrict__ X,
                                              const float* __restrict__ S,
                                              const float* __restrict__ W1x,
                                              const float* __restrict__ W1s) {
    int n = blockIdx.x * 256 + threadIdx.x;
    float s[4], x[4];
#pragma unroll
    for (int m = 0; m < 4; m++) { s[m] = S[m*Nn + n]; x[m] = X[m*Nn + n]; }
    float xe[4], se[4];
#pragma unroll
    for (int l = 0; l < 4; l++) {
        float a = 0.f, b = 0.f;
#pragma unroll
        for (int m = 0; m < 4; m++) {
            a = fmaf(__ldg(&W1x[l*4 + m]), s[m], a);
            b = fmaf(__ldg(&W1s[l*4 + m]), x[m], b);
        }
        xe[l] = a; se[l] = b;
    }
    g_E[n]      = make_float4(xe[0], xe[1], xe[2], xe[3]);
    g_E[Nn + n] = make_float4(se[0], se[1], se[2], se[3]);
    float nx = xe[0]*xe[0] + xe[1]*xe[1] + xe[2]*xe[2] + xe[3]*xe[3];
    float ns = se[0]*se[0] + se[1]*se[1] + se[2]*se[2] + se[3]*se[3];
#pragma unroll
    for (int o = 16; o; o >>= 1) {
        nx = fmaxf(nx, __shfl_xor_sync(0xFFFFFFFFu, nx, o));
        ns = fmaxf(ns, __shfl_xor_sync(0xFFFFFFFFu, ns, o));
    }
    if ((threadIdx.x & 31) == 0) {
        atomicMax(&g_RsqBits[0], __float_as_uint(nx));
        atomicMax(&g_RsqBits[1], __float_as_uint(ns));
    }
}

// fast exp2 for y <= ~0; clamps at -120 (underflow -> ~1e-36, harmless)
__device__ __forceinline__ float fexp2(float y) {
    y = fmaxf(y, -120.0f);
    float t = y + 12582912.0f;                 // 1.5 * 2^23: round-to-nearest
    int   k = __float_as_int(t) << 23;         // integer part into exponent field
    float f = y - (t - 12582912.0f);           // f in [-0.5, 0.5]
    float p = 1.3333558146e-3f;
    p = fmaf(p, f, 9.6181291056e-3f);
    p = fmaf(p, f, 5.5504108664e-2f);
    p = fmaf(p, f, 2.4022650696e-1f);
    p = fmaf(p, f, 6.9314718056e-1f);
    p = fmaf(p, f, 1.0f);
    return __int_as_float(__float_as_int(p) + k);
}

// ---------------------------------------------------------------- attention partials
__global__ void __launch_bounds__(128) k_attn() {
    __shared__ float4 sh[CHUNK];               // 16 KB
    int br = blockIdx.z;
    int s  = blockIdx.y;
    const float4* E = g_E + br * Nn;
    for (int i = threadIdx.x; i < CHUNK; i += 128) sh[i] = E[s*CHUNK + i];
    __syncthreads();

    int j = blockIdx.x * 128 + threadIdx.x;
    float4 c = E[j];
    const float L2E = 1.4426950408889634f;
    float cx = c.x*L2E, cy = c.y*L2E, cz = c.z*L2E, cw = c.w*L2E;
    float R  = sqrtf(__uint_as_float(g_RsqBits[br]));
    // -m_hat' = -|c'|*R  (upper bound on max dot, folded into the fma chain)
    float nm = -sqrtf(fmaf(cx,cx, fmaf(cy,cy, fmaf(cz,cz, cw*cw)))) * R;

    float n0 = 0.f, n1 = 0.f, n2 = 0.f, n3 = 0.f, dn = 0.f;
#pragma unroll 8
    for (int i = 0; i < CHUNK; i++) {
        float4 e = sh[i];
        float d = fmaf(e.x,cx, fmaf(e.y,cy, fmaf(e.z,cz, fmaf(e.w,cw, nm))));
        float w = fexp2(d);
        n0 = fmaf(w, e.x, n0);
        n1 = fmaf(w, e.y, n1);
        n2 = fmaf(w, e.z, n2);
        n3 = fmaf(w, e.w, n3);
        dn += w;
    }
    int p = (br*SPLITS + s)*Nn + j;
    g_pnum[p] = make_float4(n0, n1, n2, n3);
    g_pden[p] = dn;
}

// ---------------------------------------------------------------- combine -> Z8
__global__ void __launch_bounds__(256) k_combine() {
    int t  = blockIdx.x * 256 + threadIdx.x;   // 0 .. 16383
    int br = t >> 13;
    int j  = t & (Nn - 1);
    float nx = 0.f, ny = 0.f, nz = 0.f, nw = 0.f, d = 0.f;
#pragma unroll
    for (int s = 0; s < SPLITS; s++) {
        int p = (br*SPLITS + s)*Nn + j;
        float4 v = g_pnum[p];
        nx += v.x; ny += v.y; nz += v.z; nw += v.w;
        d += g_pden[p];
    }
    float inv = 1.0f / fmaxf(d, 1e-37f);
    float a[4] = { nx*inv, ny*inv, nz*inv, nw*inv };
    // Xa (4,8192) row-major flat == Xa_r (8192,4) row-major flat.
    // Z8[n][c]: c<4 from branch x, c>=4 from branch s; n*4+c' = l*8192 + j.
#pragma unroll
    for (int l = 0; l < 4; l++) {
        g_Z8[ ((l*2048) + (j >> 2)) * 8 + (j & 3) + br*4 ] = a[l];
    }
}

// ---------------------------------------------------------------- W2 GEMM (8192x8192 @ 8192x8)
#define GCH 8          // chunks over n
#define GROWS_BLK 32   // rows per block (8 warps x 4 rows)
__device__ __forceinline__ int zsw(int i) { return i ^ ((i >> 3) & 7); }

__global__ void __launch_bounds__(256) k_gemm(const float* __restrict__ W2) {
    __shared__ float4 shz[2048];               // 32 KB, xor-swizzled
    int warp = threadIdx.x >> 5, lane = threadIdx.x & 31;
    int rbase = blockIdx.x * GROWS_BLK + warp * 4;
    const float4* W4 = (const float4*)W2;
    float acc[4][8];
#pragma unroll
    for (int r = 0; r < 4; r++)
#pragma unroll
        for (int cc = 0; cc < 8; cc++) acc[r][cc] = 0.f;

    for (int ch = 0; ch < GCH; ch++) {
        __syncthreads();
#pragma unroll
        for (int q = 0; q < 8; q++) {
            int zi = q*256 + threadIdx.x;
            shz[zsw(zi)] = ((const float4*)g_Z8)[ch*2048 + zi];
        }
        __syncthreads();
        const float4* Wr0 = W4 + (size_t)(rbase+0)*2048 + ch*256;
        const float4* Wr1 = W4 + (size_t)(rbase+1)*2048 + ch*256;
        const float4* Wr2 = W4 + (size_t)(rbase+2)*2048 + ch*256;
        const float4* Wr3 = W4 + (size_t)(rbase+3)*2048 + ch*256;
#pragma unroll
        for (int it = 0; it < 8; it++) {
            int n4 = it*32 + lane;             // local float4 index within chunk
            float4 w0 = Wr0[n4], w1 = Wr1[n4], w2 = Wr2[n4], w3 = Wr3[n4];
            float wv0[4] = { w0.x, w0.y, w0.z, w0.w };
            float wv1[4] = { w1.x, w1.y, w1.z, w1.w };
            float wv2[4] = { w2.x, w2.y, w2.z, w2.w };
            float wv3[4] = { w3.x, w3.y, w3.z, w3.w };
#pragma unroll
            for (int q = 0; q < 4; q++) {
                int zi0 = n4*8 + q*2;
                float4 zl = shz[zsw(zi0)];
                float4 zh = shz[zsw(zi0 + 1)];
                acc[0][0] = fmaf(wv0[q], zl.x, acc[0][0]);
                acc[0][1] = fmaf(wv0[q], zl.y, acc[0][1]);
                acc[0][2] = fmaf(wv0[q], zl.z, acc[0][2]);
                acc[0][3] = fmaf(wv0[q], zl.w, acc[0][3]);
                acc[0][4] = fmaf(wv0[q], zh.x, acc[0][4]);
                acc[0][5] = fmaf(wv0[q], zh.y, acc[0][5]);
                acc[0][6] = fmaf(wv0[q], zh.z, acc[0][6]);
                acc[0][7] = fmaf(wv0[q], zh.w, acc[0][7]);
                acc[1][0] = fmaf(wv1[q], zl.x, acc[1][0]);
                acc[1][1] = fmaf(wv1[q], zl.y, acc[1][1]);
                acc[1][2] = fmaf(wv1[q], zl.z, acc[1][2]);
                acc[1][3] = fmaf(wv1[q], zl.w, acc[1][3]);
                acc[1][4] = fmaf(wv1[q], zh.x, acc[1][4]);
                acc[1][5] = fmaf(wv1[q], zh.y, acc[1][5]);
                acc[1][6] = fmaf(wv1[q], zh.z, acc[1][6]);
                acc[1][7] = fmaf(wv1[q], zh.w, acc[1][7]);
                acc[2][0] = fmaf(wv2[q], zl.x, acc[2][0]);
                acc[2][1] = fmaf(wv2[q], zl.y, acc[2][1]);
                acc[2][2] = fmaf(wv2[q], zl.z, acc[2][2]);
                acc[2][3] = fmaf(wv2[q], zl.w, acc[2][3]);
                acc[2][4] = fmaf(wv2[q], zh.x, acc[2][4]);
                acc[2][5] = fmaf(wv2[q], zh.y, acc[2][5]);
                acc[2][6] = fmaf(wv2[q], zh.z, acc[2][6]);
                acc[2][7] = fmaf(wv2[q], zh.w, acc[2][7]);
                acc[3][0] = fmaf(wv3[q], zl.x, acc[3][0]);
                acc[3][1] = fmaf(wv3[q], zl.y, acc[3][1]);
                acc[3][2] = fmaf(wv3[q], zl.z, acc[3][2]);
                acc[3][3] = fmaf(wv3[q], zl.w, acc[3][3]);
                acc[3][4] = fmaf(wv3[q], zh.x, acc[3][4]);
                acc[3][5] = fmaf(wv3[q], zh.y, acc[3][5]);
                acc[3][6] = fmaf(wv3[q], zh.z, acc[3][6]);
                acc[3][7] = fmaf(wv3[q], zh.w, acc[3][7]);
            }
        }
    }
    // lane reduction
#pragma unroll
    for (int r = 0; r < 4; r++)
#pragma unroll
        for (int cc = 0; cc < 8; cc++)
#pragma unroll
            for (int o = 16; o; o >>= 1)
                acc[r][cc] += __shfl_down_sync(0xFFFFFFFFu, acc[r][cc], o);
    if (lane == 0) {
#pragma unroll
        for (int r = 0; r < 4; r++) {
            int k = rbase + r;
#pragma unroll
            for (int cc = 0; cc < 8; cc++) {
                if (cc < 4) g_M[k*4 + cc] = acc[r][cc];
                else        g_M[Lc*Nn + k*4 + (cc - 4)] = acc[r][cc];
            }
        }
    }
}

// ---------------------------------------------------------------- fused epilogue + conv
__global__ void __launch_bounds__(256) k_conv(const float* __restrict__ X,
                                              const float* __restrict__ S,
                                              const float* __restrict__ wx,
                                              const float* __restrict__ bx,
                                              const float* __restrict__ ws,
                                              const float* __restrict__ bs,
                                              float* __restrict__ out) {
    __shared__ float H[2][8][264];
    __shared__ float wsm[2][8][8][3];
    __shared__ float bsm[2][8];
    int t  = threadIdx.x;
    int k0 = blockIdx.x * 256;

    for (int i = t; i < 384; i += 256) {
        int g = i / 192, r = i % 192;
        int co = r / 24, ci = (r % 24) / 3, kh = r % 3;
        const float* w = g ? ws : wx;
        wsm[g][co][ci][kh] = w[((co*8 + ci)*3 + kh)*3 + 1];  // kw = 1 only (W dim = 1)
    }
    if (t < 16) bsm[t >> 3][t & 7] = (t < 8) ? bx[t] : bs[t - 8];

    for (int i = t; i < 2*8*258; i += 256) {
        int g = i / (8*258), r = i % (8*258);
        int ci = r / 258, kk = r % 258;
        int col = k0 + kk - 1;
        float v = 0.f;
        if (col >= 0 && col < Nn) {
            if (g == 0) {
                v = (ci < 4) ? g_M[ci*Nn + col] * X[ci*Nn + col] : X[(ci - 4)*Nn + col];
            } else {
                float base = (ci < 4) ? g_M[Lc*Nn + ci*Nn + col] * X[ci*Nn + col]
                                      : S[(ci - 4)*Nn + col];
                v = base + sinf((float)col);   // sinusoid table with d_hid=1: sin(pos)
            }
        }
        H[g][ci][kk] = v;
    }
    __syncthreads();

    int k = k0 + t;
#pragma unroll
    for (int g = 0; g < 2; g++)
#pragma unroll
        for (int co = 0; co < 8; co++) {
            float a = bsm[g][co];
#pragma unroll
            for (int ci = 0; ci < 8; ci++)
#pragma unroll
                for (int kh = 0; kh < 3; kh++)
                    a = fmaf(wsm[g][co][ci][kh], H[g][ci][t + kh], a);
            out[(g*8 + co)*Nn + k] = a;
        }
}

// ---------------------------------------------------------------- launch
extern "C" void kernel_launch(void* const* d_in, const int* in_sizes, int n_in,
                              void* d_out, int out_size) {
    const float* X   = (const float*)d_in[0];
    const float* S   = (const float*)d_in[1];
    const float* W1x = (const float*)d_in[2];
    const float* W1s = (const float*)d_in[3];
    const float* W2  = (const float*)d_in[4];
    const float* cwx = (const float*)d_in[5];
    const float* cbx = (const float*)d_in[6];
    const float* cws = (const float*)d_in[7];
    const float* cbs = (const float*)d_in[8];
    float* out = (float*)d_out;

    k_init<<<1, 32>>>();
    k_prep<<<Nn/256, 256>>>(X, S, W1x, W1s);
    dim3 ga(Nn/128, SPLITS, 2);
    k_attn<<<ga, 128>>>();
    k_combine<<<2*Nn/256, 256>>>();
    k_gemm<<<Nn/GROWS_BLK, 256>>>(W2);
    k_conv<<<Nn/256, 256>>>(X, S, cwx, cbx, cws, cbs, out);
}

// round 4
// speedup vs baseline: 1.2695x; 1.2695x over previous
#include <cuda_runtime.h>
#include <math.h>

#define Lc 4
#define Nn 8192
#define SPLITS 16
#define CHUNK (Nn/SPLITS)   // 512

// ---- device scratch (no allocations allowed) ----
__device__ float4   g_E[2*Nn];                // XeT / SeT, one float4 per column
__device__ unsigned g_RsqBits[2];             // max ||xe||^2 as float bits
__device__ float4   g_pnum[2*Nn*SPLITS];      // partial numerators, [(br*Nn+j)*SPLITS+s]
__device__ float    g_pden[2*Nn*SPLITS];      // partial denominators, same index
__device__ float    g_Z8[Nn*8];               // combined RHS for W2 GEMM (8192 x 8)
__device__ float    g_M[2*Lc*Nn];             // Mx flat | Ms flat

// ---------------------------------------------------------------- init
__global__ void k_init() {
    if (threadIdx.x < 2) g_RsqBits[threadIdx.x] = 0u;
}

// ---------------------------------------------------------------- prep: Xe, Se, R
__global__ void __launch_bounds__(256) k_prep(const float* __restrict__ X,
                                              const float* __restrict__ S,
                                              const float* __restrict__ W1x,
                                              const float* __restrict__ W1s) {
    int n = blockIdx.x * 256 + threadIdx.x;
    float s[4], x[4];
#pragma unroll
    for (int m = 0; m < 4; m++) { s[m] = S[m*Nn + n]; x[m] = X[m*Nn + n]; }
    float xe[4], se[4];
#pragma unroll
    for (int l = 0; l < 4; l++) {
        float a = 0.f, b = 0.f;
#pragma unroll
        for (int m = 0; m < 4; m++) {
            a = fmaf(__ldg(&W1x[l*4 + m]), s[m], a);
            b = fmaf(__ldg(&W1s[l*4 + m]), x[m], b);
        }
        xe[l] = a; se[l] = b;
    }
    g_E[n]      = make_float4(xe[0], xe[1], xe[2], xe[3]);
    g_E[Nn + n] = make_float4(se[0], se[1], se[2], se[3]);
    float nx = xe[0]*xe[0] + xe[1]*xe[1] + xe[2]*xe[2] + xe[3]*xe[3];
    float ns = se[0]*se[0] + se[1]*se[1] + se[2]*se[2] + se[3]*se[3];
#pragma unroll
    for (int o = 16; o; o >>= 1) {
        nx = fmaxf(nx, __shfl_xor_sync(0xFFFFFFFFu, nx, o));
        ns = fmaxf(ns, __shfl_xor_sync(0xFFFFFFFFu, ns, o));
    }
    if ((threadIdx.x & 31) == 0) {
        atomicMax(&g_RsqBits[0], __float_as_uint(nx));
        atomicMax(&g_RsqBits[1], __float_as_uint(ns));
    }
}

// hardware exp2 (MUFU.EX2). Args are always <= 0 here; large-negative flushes to 0.
__device__ __forceinline__ float fex2(float y) {
    float r;
    asm("ex2.approx.f32 %0, %1;" : "=f"(r) : "f"(y));
    return r;
}

// ---------------------------------------------------------------- attention partials
// Each thread handles TWO columns (j, j+Nn/2) sharing one smem stream of e-vectors.
__global__ void __launch_bounds__(128) k_attn() {
    __shared__ float4 sh[CHUNK];               // 8 KB
    int br = blockIdx.z;
    int s  = blockIdx.y;
    const float4* E = g_E + br * Nn;
    for (int i = threadIdx.x; i < CHUNK; i += 128) sh[i] = E[s*CHUNK + i];
    __syncthreads();

    int j  = blockIdx.x * 128 + threadIdx.x;
    int j2 = j + Nn/2;
    float4 ca = E[j];
    float4 cb = E[j2];
    const float L2E = 1.4426950408889634f;
    float ax = ca.x*L2E, ay = ca.y*L2E, az = ca.z*L2E, aw = ca.w*L2E;
    float bx = cb.x*L2E, by = cb.y*L2E, bz = cb.z*L2E, bw = cb.w*L2E;
    float R  = sqrtf(__uint_as_float(g_RsqBits[br]));
    float nma = -sqrtf(fmaf(ax,ax, fmaf(ay,ay, fmaf(az,az, aw*aw)))) * R;
    float nmb = -sqrtf(fmaf(bx,bx, fmaf(by,by, fmaf(bz,bz, bw*bw)))) * R;

    float a0=0.f, a1=0.f, a2=0.f, a3=0.f, ad=0.f;
    float b0=0.f, b1=0.f, b2=0.f, b3=0.f, bd=0.f;
#pragma unroll 8
    for (int i = 0; i < CHUNK; i++) {
        float4 e = sh[i];
        float d1 = fmaf(e.x,ax, fmaf(e.y,ay, fmaf(e.z,az, fmaf(e.w,aw, nma))));
        float d2 = fmaf(e.x,bx, fmaf(e.y,by, fmaf(e.z,bz, fmaf(e.w,bw, nmb))));
        float w1 = fex2(d1);
        float w2 = fex2(d2);
        a0 = fmaf(w1, e.x, a0);  b0 = fmaf(w2, e.x, b0);
        a1 = fmaf(w1, e.y, a1);  b1 = fmaf(w2, e.y, b1);
        a2 = fmaf(w1, e.z, a2);  b2 = fmaf(w2, e.z, b2);
        a3 = fmaf(w1, e.w, a3);  b3 = fmaf(w2, e.w, b3);
        ad += w1;                bd += w2;
    }
    size_t p1 = (size_t)(br*Nn + j )*SPLITS + s;
    size_t p2 = (size_t)(br*Nn + j2)*SPLITS + s;
    g_pnum[p1] = make_float4(a0, a1, a2, a3);
    g_pden[p1] = ad;
    g_pnum[p2] = make_float4(b0, b1, b2, b3);
    g_pden[p2] = bd;
}

// ---------------------------------------------------------------- combine -> Z8
__global__ void __launch_bounds__(256) k_combine() {
    int t  = blockIdx.x * 256 + threadIdx.x;   // 0 .. 16383
    int br = t >> 13;
    int j  = t & (Nn - 1);
    const float4* pn = g_pnum + (size_t)(br*Nn + j)*SPLITS;
    const float4* pd = (const float4*)(g_pden + (size_t)(br*Nn + j)*SPLITS);
    float nx = 0.f, ny = 0.f, nz = 0.f, nw = 0.f, d = 0.f;
#pragma unroll
    for (int s = 0; s < SPLITS; s++) {
        float4 v = pn[s];
        nx += v.x; ny += v.y; nz += v.z; nw += v.w;
    }
#pragma unroll
    for (int q = 0; q < SPLITS/4; q++) {
        float4 v = pd[q];
        d += v.x + v.y + v.z + v.w;
    }
    float inv = 1.0f / fmaxf(d, 1e-37f);
    float a[4] = { nx*inv, ny*inv, nz*inv, nw*inv };
    // Xa (4,8192) row-major flat == Xa_r (8192,4) row-major flat.
    // Z8[n][c]: c<4 from branch x, c>=4 from branch s; n*4+c' = l*8192 + j.
#pragma unroll
    for (int l = 0; l < 4; l++) {
        g_Z8[ ((l*2048) + (j >> 2)) * 8 + (j & 3) + br*4 ] = a[l];
    }
}

// ---------------------------------------------------------------- W2 GEMM (8192x8192 @ 8192x8)
#define GCH 8          // chunks over n
#define GROWS_BLK 32   // rows per block (8 warps x 4 rows)
__device__ __forceinline__ int zsw(int i) { return i ^ ((i >> 3) & 7); }

__global__ void __launch_bounds__(256) k_gemm(const float* __restrict__ W2) {
    __shared__ float4 shz[2048];               // 32 KB, xor-swizzled
    int warp = threadIdx.x >> 5, lane = threadIdx.x & 31;
    int rbase = blockIdx.x * GROWS_BLK + warp * 4;
    const float4* W4 = (const float4*)W2;
    float acc[4][8];
#pragma unroll
    for (int r = 0; r < 4; r++)
#pragma unroll
        for (int cc = 0; cc < 8; cc++) acc[r][cc] = 0.f;

    for (int ch = 0; ch < GCH; ch++) {
        __syncthreads();
#pragma unroll
        for (int q = 0; q < 8; q++) {
            int zi = q*256 + threadIdx.x;
            shz[zsw(zi)] = ((const float4*)g_Z8)[ch*2048 + zi];
        }
        __syncthreads();
        const float4* Wr0 = W4 + (size_t)(rbase+0)*2048 + ch*256;
        const float4* Wr1 = W4 + (size_t)(rbase+1)*2048 + ch*256;
        const float4* Wr2 = W4 + (size_t)(rbase+2)*2048 + ch*256;
        const float4* Wr3 = W4 + (size_t)(rbase+3)*2048 + ch*256;
#pragma unroll
        for (int it = 0; it < 8; it++) {
            int n4 = it*32 + lane;             // local float4 index within chunk
            float4 w0 = Wr0[n4], w1 = Wr1[n4], w2 = Wr2[n4], w3 = Wr3[n4];
            float wv0[4] = { w0.x, w0.y, w0.z, w0.w };
            float wv1[4] = { w1.x, w1.y, w1.z, w1.w };
            float wv2[4] = { w2.x, w2.y, w2.z, w2.w };
            float wv3[4] = { w3.x, w3.y, w3.z, w3.w };
#pragma unroll
            for (int q = 0; q < 4; q++) {
                int zi0 = n4*8 + q*2;
                float4 zl = shz[zsw(zi0)];
                float4 zh = shz[zsw(zi0 + 1)];
                acc[0][0] = fmaf(wv0[q], zl.x, acc[0][0]);
                acc[0][1] = fmaf(wv0[q], zl.y, acc[0][1]);
                acc[0][2] = fmaf(wv0[q], zl.z, acc[0][2]);
                acc[0][3] = fmaf(wv0[q], zl.w, acc[0][3]);
                acc[0][4] = fmaf(wv0[q], zh.x, acc[0][4]);
                acc[0][5] = fmaf(wv0[q], zh.y, acc[0][5]);
                acc[0][6] = fmaf(wv0[q], zh.z, acc[0][6]);
                acc[0][7] = fmaf(wv0[q], zh.w, acc[0][7]);
                acc[1][0] = fmaf(wv1[q], zl.x, acc[1][0]);
                acc[1][1] = fmaf(wv1[q], zl.y, acc[1][1]);
                acc[1][2] = fmaf(wv1[q], zl.z, acc[1][2]);
                acc[1][3] = fmaf(wv1[q], zl.w, acc[1][3]);
                acc[1][4] = fmaf(wv1[q], zh.x, acc[1][4]);
                acc[1][5] = fmaf(wv1[q], zh.y, acc[1][5]);
                acc[1][6] = fmaf(wv1[q], zh.z, acc[1][6]);
                acc[1][7] = fmaf(wv1[q], zh.w, acc[1][7]);
                acc[2][0] = fmaf(wv2[q], zl.x, acc[2][0]);
                acc[2][1] = fmaf(wv2[q], zl.y, acc[2][1]);
                acc[2][2] = fmaf(wv2[q], zl.z, acc[2][2]);
                acc[2][3] = fmaf(wv2[q], zl.w, acc[2][3]);
                acc[2][4] = fmaf(wv2[q], zh.x, acc[2][4]);
                acc[2][5] = fmaf(wv2[q], zh.y, acc[2][5]);
                acc[2][6] = fmaf(wv2[q], zh.z, acc[2][6]);
                acc[2][7] = fmaf(wv2[q], zh.w, acc[2][7]);
                acc[3][0] = fmaf(wv3[q], zl.x, acc[3][0]);
                acc[3][1] = fmaf(wv3[q], zl.y, acc[3][1]);
                acc[3][2] = fmaf(wv3[q], zl.z, acc[3][2]);
                acc[3][3] = fmaf(wv3[q], zl.w, acc[3][3]);
                acc[3][4] = fmaf(wv3[q], zh.x, acc[3][4]);
                acc[3][5] = fmaf(wv3[q], zh.y, acc[3][5]);
                acc[3][6] = fmaf(wv3[q], zh.z, acc[3][6]);
                acc[3][7] = fmaf(wv3[q], zh.w, acc[3][7]);
            }
        }
    }
    // lane reduction
#pragma unroll
    for (int r = 0; r < 4; r++)
#pragma unroll
        for (int cc = 0; cc < 8; cc++)
#pragma unroll
            for (int o = 16; o; o >>= 1)
                acc[r][cc] += __shfl_down_sync(0xFFFFFFFFu, acc[r][cc], o);
    if (lane == 0) {
#pragma unroll
        for (int r = 0; r < 4; r++) {
            int k = rbase + r;
#pragma unroll
            for (int cc = 0; cc < 8; cc++) {
                if (cc < 4) g_M[k*4 + cc] = acc[r][cc];
                else        g_M[Lc*Nn + k*4 + (cc - 4)] = acc[r][cc];
            }
        }
    }
}

// ---------------------------------------------------------------- fused epilogue + conv
__global__ void __launch_bounds__(256) k_conv(const float* __restrict__ X,
                                              const float* __restrict__ S,
                                              const float* __restrict__ wx,
                                              const float* __restrict__ bx,
                                              const float* __restrict__ ws,
                                              const float* __restrict__ bs,
                                              float* __restrict__ out) {
    __shared__ float H[2][8][264];
    __shared__ float wsm[2][8][8][3];
    __shared__ float bsm[2][8];
    int t  = threadIdx.x;
    int k0 = blockIdx.x * 256;

    for (int i = t; i < 384; i += 256) {
        int g = i / 192, r = i % 192;
        int co = r / 24, ci = (r % 24) / 3, kh = r % 3;
        const float* w = g ? ws : wx;
        wsm[g][co][ci][kh] = w[((co*8 + ci)*3 + kh)*3 + 1];  // kw = 1 only (W dim = 1)
    }
    if (t < 16) bsm[t >> 3][t & 7] = (t < 8) ? bx[t] : bs[t - 8];

    for (int i = t; i < 2*8*258; i += 256) {
        int g = i / (8*258), r = i % (8*258);
        int ci = r / 258, kk = r % 258;
        int col = k0 + kk - 1;
        float v = 0.f;
        if (col >= 0 && col < Nn) {
            if (g == 0) {
                v = (ci < 4) ? g_M[ci*Nn + col] * X[ci*Nn + col] : X[(ci - 4)*Nn + col];
            } else {
                float base = (ci < 4) ? g_M[Lc*Nn + ci*Nn + col] * X[ci*Nn + col]
                                      : S[(ci - 4)*Nn + col];
                v = base + sinf((float)col);   // sinusoid table with d_hid=1: sin(pos)
            }
        }
        H[g][ci][kk] = v;
    }
    __syncthreads();

    int k = k0 + t;
#pragma unroll
    for (int g = 0; g < 2; g++)
#pragma unroll
        for (int co = 0; co < 8; co++) {
            float a = bsm[g][co];
#pragma unroll
            for (int ci = 0; ci < 8; ci++)
#pragma unroll
                for (int kh = 0; kh < 3; kh++)
                    a = fmaf(wsm[g][co][ci][kh], H[g][ci][t + kh], a);
            out[(g*8 + co)*Nn + k] = a;
        }
}

// ---------------------------------------------------------------- launch
extern "C" void kernel_launch(void* const* d_in, const int* in_sizes, int n_in,
                              void* d_out, int out_size) {
    const float* X   = (const float*)d_in[0];
    const float* S   = (const float*)d_in[1];
    const float* W1x = (const float*)d_in[2];
    const float* W1s = (const float*)d_in[3];
    const float* W2  = (const float*)d_in[4];
    const float* cwx = (const float*)d_in[5];
    const float* cbx = (const float*)d_in[6];
    const float* cws = (const float*)d_in[7];
    const float* cbs = (const float*)d_in[8];
    float* out = (float*)d_out;

    k_init<<<1, 32>>>();
    k_prep<<<Nn/256, 256>>>(X, S, W1x, W1s);
    dim3 ga(Nn/2/128, SPLITS, 2);
    k_attn<<<ga, 128>>>();
    k_combine<<<2*Nn/256, 256>>>();
    k_gemm<<<Nn/GROWS_BLK, 256>>>(W2);
    k_conv<<<Nn/256, 256>>>(X, S, cwx, cbx, cws, cbs, out);
}